// round 16
// baseline (speedup 1.0000x reference)
#include <cuda_runtime.h>
#include <cuda_fp16.h>
#include <math.h>
#include <stdint.h>
#include <cstdint>

// Problem constants
#define N_NODES 50000
#define N_EDGES 800000
#define CH 128
#define OUT_CH 6
#define N_GRAPHS 64
#define MAX_DEG 96
#define DUMMY_NODE N_NODES          // zero row appended to g_G16

// GEMM tile: M=128, N=128, K=128 (full K resident), fp16 operands in smem
#define TILE_M 128
#define SMEM_A_BYTES (TILE_M * 256)          // 128 rows x 128 fp16 = 32 KB
#define SMEM_W_BYTES (128 * 256)             // 128 rows x 128 fp16 = 32 KB
#define GEMM_SMEM_BYTES (SMEM_A_BYTES + SMEM_W_BYTES)   // 64 KB

// ---------------- static device scratch ----------------
__device__ int   g_is64;
__device__ int   g_batch[N_NODES];
__device__ int   g_cursor[N_NODES];
__device__ int   g_bucket[(size_t)N_NODES * MAX_DEG];      // src indices; tail = DUMMY_NODE
__device__ __half2 g_G16[(size_t)(N_NODES + 1) * (CH / 2)]; // +1 zero dummy row
__device__ __half2 g_H16[(size_t)N_NODES * (CH / 2)];       // layer output, fp16
__device__ float g_H6[(size_t)N_NODES * OUT_CH];
__device__ __half g_Wpk16[3][128 * 128];                    // fp16 W, pre-swizzled

// ---------------- prep: zero cursors + dtype detect + W pack + bucket prefill ----------------
__global__ void prep_kernel(const unsigned int* __restrict__ ei_words,
                            const float* __restrict__ W0,
                            const float* __restrict__ W1,
                            const float* __restrict__ W2) {
    int t = blockIdx.x * blockDim.x + threadIdx.x;
    int nthreads = gridDim.x * blockDim.x;
    if (t < N_NODES) g_cursor[t] = 0;
    if (t < 3 * 128 * 128) {
        int layer = t >> 14;
        int u = t & 16383;
        int k = u >> 7;
        int n = u & 127;
        const float* W = (layer == 0) ? W0 : (layer == 1) ? W1 : W2;
        int c = (n >> 3) ^ (k & 7);
        g_Wpk16[layer][k * 128 + (c << 3) + (n & 7)] = __float2half(W[(size_t)k * CH + n]);
    }
    // zero the dummy G16 row (64 uint per 256B row)
    if (t < 64) ((unsigned int*)(g_G16 + (size_t)DUMMY_NODE * (CH / 2)))[t] = 0u;
    // prefill bucket with DUMMY_NODE (int4 stores; 1.2M int4)
    {
        int4 dv4 = make_int4(DUMMY_NODE, DUMMY_NODE, DUMMY_NODE, DUMMY_NODE);
        int total4 = (N_NODES * MAX_DEG) / 4;
        for (int u = t; u < total4; u += nthreads)
            ((int4*)g_bucket)[u] = dv4;
    }
    if (blockIdx.x == 0) {
        __shared__ int nonzero;
        if (threadIdx.x == 0) nonzero = 0;
        __syncthreads();
        if (threadIdx.x < 128) {
            int idx = 2 * threadIdx.x + 1;   // odd words of first 128 int64s
            if (ei_words[idx] != 0u) atomicOr(&nonzero, 1);
        }
        __syncthreads();
        if (threadIdx.x == 0) g_is64 = nonzero ? 0 : 1;
    }
}

// vectorized: 4 edges per thread per step, 16B loads
__global__ void convfill_kernel(const void* __restrict__ edge_index,
                                const void* __restrict__ batch) {
    const int is64 = g_is64;
    const int tid = blockIdx.x * blockDim.x + threadIdx.x;
    const int stride = gridDim.x * blockDim.x;

    if (is64) {
        const longlong2* p2 = (const longlong2*)edge_index;   // 2 int64 per 16B
        for (int e = tid * 4; e < N_EDGES; e += stride * 4) {
            longlong2 sa = __ldg(p2 + (e >> 1));
            longlong2 sb = __ldg(p2 + (e >> 1) + 1);
            longlong2 da = __ldg(p2 + ((N_EDGES + e) >> 1));
            longlong2 db = __ldg(p2 + ((N_EDGES + e) >> 1) + 1);
            int s[4] = {(int)sa.x, (int)sa.y, (int)sb.x, (int)sb.y};
            int d[4] = {(int)da.x, (int)da.y, (int)db.x, (int)db.y};
#pragma unroll
            for (int q = 0; q < 4; q++) {
                int pos = atomicAdd(&g_cursor[d[q]], 1);
                if (pos < MAX_DEG) g_bucket[(size_t)d[q] * MAX_DEG + pos] = s[q];
            }
        }
        const longlong2* b2 = (const longlong2*)batch;
        for (int i = tid * 2; i < N_NODES; i += stride * 2) {
            longlong2 bv = __ldg(b2 + (i >> 1));
            g_batch[i] = (int)bv.x;
            if (i + 1 < N_NODES) g_batch[i + 1] = (int)bv.y;
        }
    } else {
        const int4* p4 = (const int4*)edge_index;             // 4 int32 per 16B
        for (int e = tid * 4; e < N_EDGES; e += stride * 4) {
            int4 sv = __ldg(p4 + (e >> 2));
            int4 dv = __ldg(p4 + ((N_EDGES + e) >> 2));
            int s[4] = {sv.x, sv.y, sv.z, sv.w};
            int d[4] = {dv.x, dv.y, dv.z, dv.w};
#pragma unroll
            for (int q = 0; q < 4; q++) {
                int pos = atomicAdd(&g_cursor[d[q]], 1);
                if (pos < MAX_DEG) g_bucket[(size_t)d[q] * MAX_DEG + pos] = s[q];
            }
        }
        for (int i = tid; i < N_NODES; i += stride)
            g_batch[i] = ((const int*)batch)[i];
    }
}

// ---------------- ldmatrix wrappers ----------------
__device__ __forceinline__ void ldsm_x4(uint32_t& r0, uint32_t& r1,
                                        uint32_t& r2, uint32_t& r3, uint32_t addr) {
    asm volatile("ldmatrix.sync.aligned.m8n8.x4.shared.b16 {%0,%1,%2,%3}, [%4];"
                 : "=r"(r0), "=r"(r1), "=r"(r2), "=r"(r3) : "r"(addr));
}
__device__ __forceinline__ void ldsm_x4_t(uint32_t& r0, uint32_t& r1,
                                          uint32_t& r2, uint32_t& r3, uint32_t addr) {
    asm volatile("ldmatrix.sync.aligned.m8n8.x4.trans.shared.b16 {%0,%1,%2,%3}, [%4];"
                 : "=r"(r0), "=r"(r1), "=r"(r2), "=r"(r3) : "r"(addr));
}

// ---------------- fp16 TC GEMM: G16 = fp16(dinv .* (A @ W)) ----------------
// TILE_M=128: 8 warps in 4(M)x2(N) grid; each warp 32 rows x 64 cols.
template <bool FP16A>
__global__ __launch_bounds__(256)
void gemm_fp16_kernel(const float* __restrict__ A32, const __half* __restrict__ Wpk) {
    extern __shared__ char smem[];
    char* smA = smem;                       // [m:128][256B swizzled]
    char* smW = smem + SMEM_A_BYTES;        // [k:128][256B swizzled]

    const int tid = threadIdx.x;
    const int block_row = blockIdx.x * TILE_M;

    if (!FP16A) {
#pragma unroll
        for (int it = 0; it < 8; it++) {
            int u = tid + it * 256;         // 2048 chunks (128 rows x 16)
            int m = u >> 4;
            int c = u & 15;
            int gm = block_row + m;
            if (gm >= N_NODES) gm = N_NODES - 1;
            float4 v0 = __ldg((const float4*)(A32 + (size_t)gm * CH + c * 8));
            float4 v1 = __ldg((const float4*)(A32 + (size_t)gm * CH + c * 8 + 4));
            uint4 st;
            *(__half2*)&st.x = __floats2half2_rn(v0.x, v0.y);
            *(__half2*)&st.y = __floats2half2_rn(v0.z, v0.w);
            *(__half2*)&st.z = __floats2half2_rn(v1.x, v1.y);
            *(__half2*)&st.w = __floats2half2_rn(v1.z, v1.w);
            *(uint4*)(smA + m * 256 + ((c ^ (m & 7)) << 4)) = st;
        }
    } else {
#pragma unroll
        for (int it = 0; it < 8; it++) {
            int u = tid + it * 256;
            int m = u >> 4;
            int c = u & 15;
            int gm = block_row + m;
            if (gm >= N_NODES) gm = N_NODES - 1;
            uint4 v = __ldg((const uint4*)g_H16 + (size_t)gm * 16 + c);
            *(uint4*)(smA + m * 256 + ((c ^ (m & 7)) << 4)) = v;
        }
    }
#pragma unroll
    for (int it = 0; it < 8; it++) {
        int u = tid + it * 256;             // 2048 chunks
        ((uint4*)smW)[u] = __ldg((const uint4*)Wpk + u);
    }
    __syncthreads();

    const int lane = tid & 31;
    const int warp = tid >> 5;
    const int wm = (warp & 3) * 32;       // 4 warps along M (32 rows each)
    const int wn = (warp >> 2) * 64;      // 2 warps along N (64 cols each)

    const int lq = lane >> 2;             // 0..7
    const int lr = lane & 3;              // 0..3
    const int l7 = lane & 7;
    const int l8 = (lane >> 3) & 1;
    const int l16 = lane >> 4;            // 0..1

    uint32_t smA_u = (uint32_t)__cvta_generic_to_shared(smA);
    uint32_t smW_u = (uint32_t)__cvta_generic_to_shared(smW);

    float c[2][8][4];
#pragma unroll
    for (int mt = 0; mt < 2; mt++)
#pragma unroll
        for (int nt = 0; nt < 8; nt++)
#pragma unroll
            for (int q = 0; q < 4; q++) c[mt][nt][q] = 0.0f;

    const int arow_base = wm + l7 + l8 * 8;
    const int brow_base = l7 + l8 * 8;

#pragma unroll
    for (int ks = 0; ks < 8; ks++) {
        uint32_t a[2][4];
#pragma unroll
        for (int mt = 0; mt < 2; mt++) {
            int r = arow_base + mt * 16;
            int chunk = ((ks << 1) | l16) ^ (r & 7);
            ldsm_x4(a[mt][0], a[mt][1], a[mt][2], a[mt][3],
                    smA_u + r * 256 + (chunk << 4));
        }
        uint32_t b[4][4];
#pragma unroll
        for (int nh = 0; nh < 4; nh++) {
            int kr = ks * 16 + brow_base;
            int nchunk = ((wn >> 3) + nh * 2 + l16) ^ (kr & 7);
            ldsm_x4_t(b[nh][0], b[nh][1], b[nh][2], b[nh][3],
                      smW_u + kr * 256 + (nchunk << 4));
        }
#pragma unroll
        for (int nh = 0; nh < 4; nh++)
#pragma unroll
            for (int half = 0; half < 2; half++) {
                int nt = nh * 2 + half;
                uint32_t b0 = b[nh][half * 2];
                uint32_t b1 = b[nh][half * 2 + 1];
#pragma unroll
                for (int mt = 0; mt < 2; mt++) {
                    asm volatile(
                        "mma.sync.aligned.m16n8k16.row.col.f32.f16.f16.f32 "
                        "{%0,%1,%2,%3}, {%4,%5,%6,%7}, {%8,%9}, {%0,%1,%2,%3};"
                        : "+f"(c[mt][nt][0]), "+f"(c[mt][nt][1]),
                          "+f"(c[mt][nt][2]), "+f"(c[mt][nt][3])
                        : "r"(a[mt][0]), "r"(a[mt][1]), "r"(a[mt][2]), "r"(a[mt][3]),
                          "r"(b0), "r"(b1));
                }
            }
    }

    // Epilogue: dv = rsqrt(deg+1) inline, pack to fp16 pairs
#pragma unroll
    for (int mt = 0; mt < 2; mt++) {
        int r0 = block_row + wm + mt * 16 + lq;
        int r1 = r0 + 8;
        if (r0 < N_NODES) {
            float s = rsqrtf((float)g_cursor[r0] + 1.0f);
#pragma unroll
            for (int nt = 0; nt < 8; nt++)
                g_G16[(size_t)r0 * (CH / 2) + (wn >> 1) + nt * 4 + lr] =
                    __floats2half2_rn(c[mt][nt][0] * s, c[mt][nt][1] * s);
        }
        if (r1 < N_NODES) {
            float s = rsqrtf((float)g_cursor[r1] + 1.0f);
#pragma unroll
            for (int nt = 0; nt < 8; nt++)
                g_G16[(size_t)r1 * (CH / 2) + (wn >> 1) + nt * 4 + lr] =
                    __floats2half2_rn(c[mt][nt][2] * s, c[mt][nt][3] * s);
        }
    }
}

// ---------------- Aggregation ----------------
// H[i] = tanh(dv_i*(g16_i + sum_j g16_j) + b),  g16_k = dv_k*G_k (pre-scaled)
// Bucket tails are DUMMY_NODE (zero row) -> fully unconditional gathers.
template <bool LAST>
__global__ __launch_bounds__(256)
void agg_kernel_t(const float* __restrict__ b,
                  const float* __restrict__ Wl, const float* __restrict__ bl) {
    const int lane = threadIdx.x & 31;
    const int warp = (blockIdx.x * blockDim.x + threadIdx.x) >> 5;
    if (warp >= N_NODES) return;
    const int i = warp;

    const int cur = g_cursor[i];
    const float dv = rsqrtf((float)cur + 1.0f);
    int deg = cur > MAX_DEG ? MAX_DEG : cur;

    const uint2* Gb = (const uint2*)g_G16;
    uint2 sv = __ldg(Gb + (size_t)i * 32 + lane);   // 32 uint2 per row
    float2 f0 = __half22float2(*(__half2*)&sv.x);
    float2 f1 = __half22float2(*(__half2*)&sv.y);
    float4 acc = make_float4(f0.x, f0.y, f1.x, f1.y);

    const int* bk = g_bucket + (size_t)i * MAX_DEG;

    for (int j = 0; j < deg; j += 8) {
        int4 ia = *(const int4*)(bk + j);         // tail slots hold DUMMY_NODE
        int4 ib = *(const int4*)(bk + j + 4);
        uint2 v0 = __ldg(Gb + (size_t)ia.x * 32 + lane);
        uint2 v1 = __ldg(Gb + (size_t)ia.y * 32 + lane);
        uint2 v2 = __ldg(Gb + (size_t)ia.z * 32 + lane);
        uint2 v3 = __ldg(Gb + (size_t)ia.w * 32 + lane);
        uint2 v4 = __ldg(Gb + (size_t)ib.x * 32 + lane);
        uint2 v5 = __ldg(Gb + (size_t)ib.y * 32 + lane);
        uint2 v6 = __ldg(Gb + (size_t)ib.z * 32 + lane);
        uint2 v7 = __ldg(Gb + (size_t)ib.w * 32 + lane);
        __half2 c0 = __hadd2(__hadd2(__hadd2(*(__half2*)&v0.x, *(__half2*)&v1.x),
                                     __hadd2(*(__half2*)&v2.x, *(__half2*)&v3.x)),
                             __hadd2(__hadd2(*(__half2*)&v4.x, *(__half2*)&v5.x),
                                     __hadd2(*(__half2*)&v6.x, *(__half2*)&v7.x)));
        __half2 c1 = __hadd2(__hadd2(__hadd2(*(__half2*)&v0.y, *(__half2*)&v1.y),
                                     __hadd2(*(__half2*)&v2.y, *(__half2*)&v3.y)),
                             __hadd2(__hadd2(*(__half2*)&v4.y, *(__half2*)&v5.y),
                                     __hadd2(*(__half2*)&v6.y, *(__half2*)&v7.y)));
        float2 p0 = __half22float2(c0);
        float2 p1 = __half22float2(c1);
        acc.x += p0.x; acc.y += p0.y; acc.z += p1.x; acc.w += p1.y;
    }

    float4 bb = *(const float4*)(b + lane * 4);
    float4 o;
    o.x = tanhf(fmaf(dv, acc.x, bb.x));
    o.y = tanhf(fmaf(dv, acc.y, bb.y));
    o.z = tanhf(fmaf(dv, acc.z, bb.z));
    o.w = tanhf(fmaf(dv, acc.w, bb.w));

    if (!LAST) {
        uint2 st;
        *(__half2*)&st.x = __floats2half2_rn(o.x, o.y);
        *(__half2*)&st.y = __floats2half2_rn(o.z, o.w);
        *((uint2*)g_H16 + (size_t)i * 32 + lane) = st;
    } else {
        int k = lane * 4;
#pragma unroll
        for (int cidx = 0; cidx < OUT_CH; cidx++) {
            float p = o.x * Wl[(k + 0) * OUT_CH + cidx]
                    + o.y * Wl[(k + 1) * OUT_CH + cidx]
                    + o.z * Wl[(k + 2) * OUT_CH + cidx]
                    + o.w * Wl[(k + 3) * OUT_CH + cidx];
#pragma unroll
            for (int off = 16; off > 0; off >>= 1)
                p += __shfl_xor_sync(0xffffffffu, p, off);
            if (lane == 0) g_H6[(size_t)i * OUT_CH + cidx] = tanhf(p + bl[cidx]);
        }
    }
}

// ---------------- Pool ----------------
__global__ __launch_bounds__(256)
void pool_kernel(float* __restrict__ out) {
    const int g = blockIdx.x;
    __shared__ int s_lo, s_hi;
    __shared__ float ssum[OUT_CH];
    if (threadIdx.x == 0) {
        int lo = 0, hi = N_NODES;
        while (lo < hi) { int m = (lo + hi) >> 1; if (g_batch[m] < g) lo = m + 1; else hi = m; }
        s_lo = lo;
        int lo2 = lo, hi2 = N_NODES;
        while (lo2 < hi2) { int m = (lo2 + hi2) >> 1; if (g_batch[m] < g + 1) lo2 = m + 1; else hi2 = m; }
        s_hi = lo2;
    }
    if (threadIdx.x < OUT_CH) ssum[threadIdx.x] = 0.0f;
    __syncthreads();
    int lo = s_lo, hi = s_hi;
    float loc[OUT_CH];
#pragma unroll
    for (int c = 0; c < OUT_CH; c++) loc[c] = 0.0f;
    for (int i = lo + threadIdx.x; i < hi; i += blockDim.x) {
#pragma unroll
        for (int c = 0; c < OUT_CH; c++) loc[c] += g_H6[(size_t)i * OUT_CH + c];
    }
#pragma unroll
    for (int c = 0; c < OUT_CH; c++) {
#pragma unroll
        for (int off = 16; off > 0; off >>= 1)
            loc[c] += __shfl_xor_sync(0xffffffffu, loc[c], off);
    }
    if ((threadIdx.x & 31) == 0) {
#pragma unroll
        for (int c = 0; c < OUT_CH; c++) atomicAdd(&ssum[c], loc[c]);
    }
    __syncthreads();
    if (threadIdx.x < OUT_CH) {
        float cnt = (float)(hi - lo);
        if (cnt < 1.0f) cnt = 1.0f;
        out[g * OUT_CH + threadIdx.x] = ssum[threadIdx.x] / cnt;
    }
}

// ---------------- launch ----------------
extern "C" void kernel_launch(void* const* d_in, const int* in_sizes, int n_in,
                              void* d_out, int out_size) {
    const float* x   = (const float*)d_in[0];
    const void*  ei  = d_in[1];
    const void*  bat = d_in[2];
    const float* W0  = (const float*)d_in[3];
    const float* b0  = (const float*)d_in[4];
    const float* W1  = (const float*)d_in[5];
    const float* b1  = (const float*)d_in[6];
    const float* W2  = (const float*)d_in[7];
    const float* b2  = (const float*)d_in[8];
    const float* Wl  = (const float*)d_in[9];
    const float* bl  = (const float*)d_in[10];
    float* out = (float*)d_out;

    __half* Wpk;
    cudaGetSymbolAddress((void**)&Wpk, g_Wpk16);

    cudaFuncSetAttribute(gemm_fp16_kernel<false>,
                         cudaFuncAttributeMaxDynamicSharedMemorySize,
                         GEMM_SMEM_BYTES);
    cudaFuncSetAttribute(gemm_fp16_kernel<true>,
                         cudaFuncAttributeMaxDynamicSharedMemorySize,
                         GEMM_SMEM_BYTES);

    prep_kernel<<<(N_NODES + 255) / 256, 256>>>((const unsigned int*)ei, W0, W1, W2);
    convfill_kernel<<<782, 256>>>(ei, bat);

    const int gemm_grid = (N_NODES + TILE_M - 1) / TILE_M;   // 391
    const int agg_grid  = (N_NODES * 32 + 255) / 256;

    gemm_fp16_kernel<false><<<gemm_grid, 256, GEMM_SMEM_BYTES>>>(x, Wpk);
    agg_kernel_t<false><<<agg_grid, 256>>>(b0, Wl, bl);
    gemm_fp16_kernel<true><<<gemm_grid, 256, GEMM_SMEM_BYTES>>>(nullptr, Wpk + 128 * 128);
    agg_kernel_t<false><<<agg_grid, 256>>>(b1, Wl, bl);
    gemm_fp16_kernel<true><<<gemm_grid, 256, GEMM_SMEM_BYTES>>>(nullptr, Wpk + 2 * 128 * 128);
    agg_kernel_t<true><<<agg_grid, 256>>>(b2, Wl, bl);

    pool_kernel<<<N_GRAPHS, 256>>>(out);
}

// round 17
// speedup vs baseline: 1.0249x; 1.0249x over previous
#include <cuda_runtime.h>
#include <cuda_fp16.h>
#include <math.h>
#include <stdint.h>
#include <cstdint>

// Problem constants
#define N_NODES 50000
#define N_EDGES 800000
#define CH 128
#define OUT_CH 6
#define N_GRAPHS 64
#define MAX_DEG 96
#define DUMMY_NODE N_NODES          // zero row appended to g_G16

// GEMM tile: M=128, N=128, K=128 (full K resident), fp16 operands in smem
#define TILE_M 128
#define SMEM_A_BYTES (TILE_M * 256)          // 128 rows x 128 fp16 = 32 KB
#define SMEM_W_BYTES (128 * 256)             // 128 rows x 128 fp16 = 32 KB
#define GEMM_SMEM_BYTES (SMEM_A_BYTES + SMEM_W_BYTES)   // 64 KB

// ---------------- static device scratch ----------------
__device__ int   g_is64;
__device__ int   g_batch[N_NODES];
__device__ int   g_cursor[N_NODES];
__device__ int   g_bucket[(size_t)N_NODES * MAX_DEG];      // src indices; padded tail = DUMMY
__device__ __half2 g_G16[(size_t)(N_NODES + 1) * (CH / 2)]; // +1 zero dummy row
__device__ __half2 g_H16[(size_t)N_NODES * (CH / 2)];       // layer output, fp16
__device__ float g_H6[(size_t)N_NODES * OUT_CH];
__device__ __half g_Wpk16[3][128 * 128];                    // fp16 W, pre-swizzled

// ---------------- prep: zero cursors + dtype detect + W pack + dummy row ----------------
__global__ void prep_kernel(const unsigned int* __restrict__ ei_words,
                            const float* __restrict__ W0,
                            const float* __restrict__ W1,
                            const float* __restrict__ W2) {
    int t = blockIdx.x * blockDim.x + threadIdx.x;
    if (t < N_NODES) g_cursor[t] = 0;
    if (t < 3 * 128 * 128) {
        int layer = t >> 14;
        int u = t & 16383;
        int k = u >> 7;
        int n = u & 127;
        const float* W = (layer == 0) ? W0 : (layer == 1) ? W1 : W2;
        int c = (n >> 3) ^ (k & 7);
        g_Wpk16[layer][k * 128 + (c << 3) + (n & 7)] = __float2half(W[(size_t)k * CH + n]);
    }
    // zero the dummy G16 row (64 uint per 256B row)
    if (t < 64) ((unsigned int*)(g_G16 + (size_t)DUMMY_NODE * (CH / 2)))[t] = 0u;
    if (blockIdx.x == 0) {
        __shared__ int nonzero;
        if (threadIdx.x == 0) nonzero = 0;
        __syncthreads();
        if (threadIdx.x < 128) {
            int idx = 2 * threadIdx.x + 1;   // odd words of first 128 int64s
            if (ei_words[idx] != 0u) atomicOr(&nonzero, 1);
        }
        __syncthreads();
        if (threadIdx.x == 0) g_is64 = nonzero ? 0 : 1;
    }
}

// vectorized: 4 edges per thread per step, 16B loads
__global__ void convfill_kernel(const void* __restrict__ edge_index,
                                const void* __restrict__ batch) {
    const int is64 = g_is64;
    const int tid = blockIdx.x * blockDim.x + threadIdx.x;
    const int stride = gridDim.x * blockDim.x;

    if (is64) {
        const longlong2* p2 = (const longlong2*)edge_index;   // 2 int64 per 16B
        for (int e = tid * 4; e < N_EDGES; e += stride * 4) {
            longlong2 sa = __ldg(p2 + (e >> 1));
            longlong2 sb = __ldg(p2 + (e >> 1) + 1);
            longlong2 da = __ldg(p2 + ((N_EDGES + e) >> 1));
            longlong2 db = __ldg(p2 + ((N_EDGES + e) >> 1) + 1);
            int s[4] = {(int)sa.x, (int)sa.y, (int)sb.x, (int)sb.y};
            int d[4] = {(int)da.x, (int)da.y, (int)db.x, (int)db.y};
#pragma unroll
            for (int q = 0; q < 4; q++) {
                int pos = atomicAdd(&g_cursor[d[q]], 1);
                if (pos < MAX_DEG) g_bucket[(size_t)d[q] * MAX_DEG + pos] = s[q];
            }
        }
        const longlong2* b2 = (const longlong2*)batch;
        for (int i = tid * 2; i < N_NODES; i += stride * 2) {
            longlong2 bv = __ldg(b2 + (i >> 1));
            g_batch[i] = (int)bv.x;
            if (i + 1 < N_NODES) g_batch[i + 1] = (int)bv.y;
        }
    } else {
        const int4* p4 = (const int4*)edge_index;             // 4 int32 per 16B
        for (int e = tid * 4; e < N_EDGES; e += stride * 4) {
            int4 sv = __ldg(p4 + (e >> 2));
            int4 dv = __ldg(p4 + ((N_EDGES + e) >> 2));
            int s[4] = {sv.x, sv.y, sv.z, sv.w};
            int d[4] = {dv.x, dv.y, dv.z, dv.w};
#pragma unroll
            for (int q = 0; q < 4; q++) {
                int pos = atomicAdd(&g_cursor[d[q]], 1);
                if (pos < MAX_DEG) g_bucket[(size_t)d[q] * MAX_DEG + pos] = s[q];
            }
        }
        for (int i = tid; i < N_NODES; i += stride)
            g_batch[i] = ((const int*)batch)[i];
    }
}

// ---------------- pad: fill [deg, roundup8(max(deg, deg_pair))) with DUMMY ----------------
// pair = i^1 (agg runs 2 nodes per warp with uniform trip count = pair max)
__global__ void pad_kernel() {
    int i = blockIdx.x * blockDim.x + threadIdx.x;
    if (i >= N_NODES) return;
    int deg  = min(g_cursor[i], MAX_DEG);
    int degp = min(g_cursor[i ^ 1], MAX_DEG);
    int m8 = (max(deg, degp) + 7) & ~7;
    int* bk = g_bucket + (size_t)i * MAX_DEG;
    for (int j = deg; j < m8; j++) bk[j] = DUMMY_NODE;
}

// ---------------- ldmatrix wrappers ----------------
__device__ __forceinline__ void ldsm_x4(uint32_t& r0, uint32_t& r1,
                                        uint32_t& r2, uint32_t& r3, uint32_t addr) {
    asm volatile("ldmatrix.sync.aligned.m8n8.x4.shared.b16 {%0,%1,%2,%3}, [%4];"
                 : "=r"(r0), "=r"(r1), "=r"(r2), "=r"(r3) : "r"(addr));
}
__device__ __forceinline__ void ldsm_x4_t(uint32_t& r0, uint32_t& r1,
                                          uint32_t& r2, uint32_t& r3, uint32_t addr) {
    asm volatile("ldmatrix.sync.aligned.m8n8.x4.trans.shared.b16 {%0,%1,%2,%3}, [%4];"
                 : "=r"(r0), "=r"(r1), "=r"(r2), "=r"(r3) : "r"(addr));
}

// ---------------- fp16 TC GEMM: G16 = fp16(dinv .* (A @ W)) ----------------
// TILE_M=128: 8 warps in 4(M)x2(N) grid; each warp 32 rows x 64 cols.
template <bool FP16A>
__global__ __launch_bounds__(256)
void gemm_fp16_kernel(const float* __restrict__ A32, const __half* __restrict__ Wpk) {
    extern __shared__ char smem[];
    char* smA = smem;                       // [m:128][256B swizzled]
    char* smW = smem + SMEM_A_BYTES;        // [k:128][256B swizzled]

    const int tid = threadIdx.x;
    const int block_row = blockIdx.x * TILE_M;

    if (!FP16A) {
#pragma unroll
        for (int it = 0; it < 8; it++) {
            int u = tid + it * 256;         // 2048 chunks (128 rows x 16)
            int m = u >> 4;
            int c = u & 15;
            int gm = block_row + m;
            if (gm >= N_NODES) gm = N_NODES - 1;
            float4 v0 = __ldg((const float4*)(A32 + (size_t)gm * CH + c * 8));
            float4 v1 = __ldg((const float4*)(A32 + (size_t)gm * CH + c * 8 + 4));
            uint4 st;
            *(__half2*)&st.x = __floats2half2_rn(v0.x, v0.y);
            *(__half2*)&st.y = __floats2half2_rn(v0.z, v0.w);
            *(__half2*)&st.z = __floats2half2_rn(v1.x, v1.y);
            *(__half2*)&st.w = __floats2half2_rn(v1.z, v1.w);
            *(uint4*)(smA + m * 256 + ((c ^ (m & 7)) << 4)) = st;
        }
    } else {
#pragma unroll
        for (int it = 0; it < 8; it++) {
            int u = tid + it * 256;
            int m = u >> 4;
            int c = u & 15;
            int gm = block_row + m;
            if (gm >= N_NODES) gm = N_NODES - 1;
            uint4 v = __ldg((const uint4*)g_H16 + (size_t)gm * 16 + c);
            *(uint4*)(smA + m * 256 + ((c ^ (m & 7)) << 4)) = v;
        }
    }
#pragma unroll
    for (int it = 0; it < 8; it++) {
        int u = tid + it * 256;             // 2048 chunks
        ((uint4*)smW)[u] = __ldg((const uint4*)Wpk + u);
    }
    __syncthreads();

    const int lane = tid & 31;
    const int warp = tid >> 5;
    const int wm = (warp & 3) * 32;       // 4 warps along M (32 rows each)
    const int wn = (warp >> 2) * 64;      // 2 warps along N (64 cols each)

    const int lq = lane >> 2;             // 0..7
    const int lr = lane & 3;              // 0..3
    const int l7 = lane & 7;
    const int l8 = (lane >> 3) & 1;
    const int l16 = lane >> 4;            // 0..1

    uint32_t smA_u = (uint32_t)__cvta_generic_to_shared(smA);
    uint32_t smW_u = (uint32_t)__cvta_generic_to_shared(smW);

    float c[2][8][4];
#pragma unroll
    for (int mt = 0; mt < 2; mt++)
#pragma unroll
        for (int nt = 0; nt < 8; nt++)
#pragma unroll
            for (int q = 0; q < 4; q++) c[mt][nt][q] = 0.0f;

    const int arow_base = wm + l7 + l8 * 8;
    const int brow_base = l7 + l8 * 8;

#pragma unroll
    for (int ks = 0; ks < 8; ks++) {
        uint32_t a[2][4];
#pragma unroll
        for (int mt = 0; mt < 2; mt++) {
            int r = arow_base + mt * 16;
            int chunk = ((ks << 1) | l16) ^ (r & 7);
            ldsm_x4(a[mt][0], a[mt][1], a[mt][2], a[mt][3],
                    smA_u + r * 256 + (chunk << 4));
        }
        uint32_t b[4][4];
#pragma unroll
        for (int nh = 0; nh < 4; nh++) {
            int kr = ks * 16 + brow_base;
            int nchunk = ((wn >> 3) + nh * 2 + l16) ^ (kr & 7);
            ldsm_x4_t(b[nh][0], b[nh][1], b[nh][2], b[nh][3],
                      smW_u + kr * 256 + (nchunk << 4));
        }
#pragma unroll
        for (int nh = 0; nh < 4; nh++)
#pragma unroll
            for (int half = 0; half < 2; half++) {
                int nt = nh * 2 + half;
                uint32_t b0 = b[nh][half * 2];
                uint32_t b1 = b[nh][half * 2 + 1];
#pragma unroll
                for (int mt = 0; mt < 2; mt++) {
                    asm volatile(
                        "mma.sync.aligned.m16n8k16.row.col.f32.f16.f16.f32 "
                        "{%0,%1,%2,%3}, {%4,%5,%6,%7}, {%8,%9}, {%0,%1,%2,%3};"
                        : "+f"(c[mt][nt][0]), "+f"(c[mt][nt][1]),
                          "+f"(c[mt][nt][2]), "+f"(c[mt][nt][3])
                        : "r"(a[mt][0]), "r"(a[mt][1]), "r"(a[mt][2]), "r"(a[mt][3]),
                          "r"(b0), "r"(b1));
                }
            }
    }

    // Epilogue: dv = rsqrt(deg+1) inline, pack to fp16 pairs
#pragma unroll
    for (int mt = 0; mt < 2; mt++) {
        int r0 = block_row + wm + mt * 16 + lq;
        int r1 = r0 + 8;
        if (r0 < N_NODES) {
            float s = rsqrtf((float)g_cursor[r0] + 1.0f);
#pragma unroll
            for (int nt = 0; nt < 8; nt++)
                g_G16[(size_t)r0 * (CH / 2) + (wn >> 1) + nt * 4 + lr] =
                    __floats2half2_rn(c[mt][nt][0] * s, c[mt][nt][1] * s);
        }
        if (r1 < N_NODES) {
            float s = rsqrtf((float)g_cursor[r1] + 1.0f);
#pragma unroll
            for (int nt = 0; nt < 8; nt++)
                g_G16[(size_t)r1 * (CH / 2) + (wn >> 1) + nt * 4 + lr] =
                    __floats2half2_rn(c[mt][nt][2] * s, c[mt][nt][3] * s);
        }
    }
}

// ---------------- Aggregation: 2 nodes per warp, 16 lanes/node, uint4 gathers ----------------
// H[i] = tanh(dv_i*(g16_i + sum_j g16_j) + b);  g16_k pre-scaled by dv_k.
// Uniform trip count = roundup8(max(degA, degB)); pad_kernel guarantees those
// bucket slots hold DUMMY_NODE (zero row) -> fully unconditional.
template <bool LAST>
__global__ __launch_bounds__(256)
void agg_kernel_t(const float* __restrict__ b,
                  const float* __restrict__ Wl, const float* __restrict__ bl) {
    const int lane = threadIdx.x & 31;
    const int warpId = (blockIdx.x * blockDim.x + threadIdx.x) >> 5;
    const int half = lane >> 4;
    const int l16 = lane & 15;
    const int node = warpId * 2 + half;
    if (node >= N_NODES) return;

    const int cur = g_cursor[node];
    const float dv = rsqrtf((float)cur + 1.0f);
    int deg = cur > MAX_DEG ? MAX_DEG : cur;
    int mdeg = max(deg, __shfl_xor_sync(0xffffffffu, deg, 16));
    const int m8 = (mdeg + 7) & ~7;

    const uint4* Gb = (const uint4*)g_G16;   // 16 uint4 per 256B row
    uint4 sv = __ldg(Gb + (size_t)node * 16 + l16);
    float2 s0 = __half22float2(*(__half2*)&sv.x);
    float2 s1 = __half22float2(*(__half2*)&sv.y);
    float2 s2 = __half22float2(*(__half2*)&sv.z);
    float2 s3 = __half22float2(*(__half2*)&sv.w);
    float acc[8] = {s0.x, s0.y, s1.x, s1.y, s2.x, s2.y, s3.x, s3.y};

    const int* bk = g_bucket + (size_t)node * MAX_DEG;

    for (int j = 0; j < m8; j += 8) {
        int4 ia = *(const int4*)(bk + j);        // broadcast within 16-lane half
        int4 ib = *(const int4*)(bk + j + 4);
        uint4 v0 = __ldg(Gb + (size_t)ia.x * 16 + l16);
        uint4 v1 = __ldg(Gb + (size_t)ia.y * 16 + l16);
        uint4 v2 = __ldg(Gb + (size_t)ia.z * 16 + l16);
        uint4 v3 = __ldg(Gb + (size_t)ia.w * 16 + l16);
        uint4 v4 = __ldg(Gb + (size_t)ib.x * 16 + l16);
        uint4 v5 = __ldg(Gb + (size_t)ib.y * 16 + l16);
        uint4 v6 = __ldg(Gb + (size_t)ib.z * 16 + l16);
        uint4 v7 = __ldg(Gb + (size_t)ib.w * 16 + l16);
        __half2 c0 = __hadd2(__hadd2(__hadd2(*(__half2*)&v0.x, *(__half2*)&v1.x),
                                     __hadd2(*(__half2*)&v2.x, *(__half2*)&v3.x)),
                             __hadd2(__hadd2(*(__half2*)&v4.x, *(__half2*)&v5.x),
                                     __hadd2(*(__half2*)&v6.x, *(__half2*)&v7.x)));
        __half2 c1 = __hadd2(__hadd2(__hadd2(*(__half2*)&v0.y, *(__half2*)&v1.y),
                                     __hadd2(*(__half2*)&v2.y, *(__half2*)&v3.y)),
                             __hadd2(__hadd2(*(__half2*)&v4.y, *(__half2*)&v5.y),
                                     __hadd2(*(__half2*)&v6.y, *(__half2*)&v7.y)));
        __half2 c2 = __hadd2(__hadd2(__hadd2(*(__half2*)&v0.z, *(__half2*)&v1.z),
                                     __hadd2(*(__half2*)&v2.z, *(__half2*)&v3.z)),
                             __hadd2(__hadd2(*(__half2*)&v4.z, *(__half2*)&v5.z),
                                     __hadd2(*(__half2*)&v6.z, *(__half2*)&v7.z)));
        __half2 c3 = __hadd2(__hadd2(__hadd2(*(__half2*)&v0.w, *(__half2*)&v1.w),
                                     __hadd2(*(__half2*)&v2.w, *(__half2*)&v3.w)),
                             __hadd2(__hadd2(*(__half2*)&v4.w, *(__half2*)&v5.w),
                                     __hadd2(*(__half2*)&v6.w, *(__half2*)&v7.w)));
        float2 p0 = __half22float2(c0);
        float2 p1 = __half22float2(c1);
        float2 p2 = __half22float2(c2);
        float2 p3 = __half22float2(c3);
        acc[0] += p0.x; acc[1] += p0.y; acc[2] += p1.x; acc[3] += p1.y;
        acc[4] += p2.x; acc[5] += p2.y; acc[6] += p3.x; acc[7] += p3.y;
    }

    const float* bptr = b + l16 * 8;
    float4 bb0 = *(const float4*)bptr;
    float4 bb1 = *(const float4*)(bptr + 4);
    float o[8];
    o[0] = tanhf(fmaf(dv, acc[0], bb0.x));
    o[1] = tanhf(fmaf(dv, acc[1], bb0.y));
    o[2] = tanhf(fmaf(dv, acc[2], bb0.z));
    o[3] = tanhf(fmaf(dv, acc[3], bb0.w));
    o[4] = tanhf(fmaf(dv, acc[4], bb1.x));
    o[5] = tanhf(fmaf(dv, acc[5], bb1.y));
    o[6] = tanhf(fmaf(dv, acc[6], bb1.z));
    o[7] = tanhf(fmaf(dv, acc[7], bb1.w));

    if (!LAST) {
        uint4 st;
        *(__half2*)&st.x = __floats2half2_rn(o[0], o[1]);
        *(__half2*)&st.y = __floats2half2_rn(o[2], o[3]);
        *(__half2*)&st.z = __floats2half2_rn(o[4], o[5]);
        *(__half2*)&st.w = __floats2half2_rn(o[6], o[7]);
        ((uint4*)g_H16)[(size_t)node * 16 + l16] = st;
    } else {
        int k = l16 * 8;
#pragma unroll
        for (int cidx = 0; cidx < OUT_CH; cidx++) {
            float p = 0.0f;
#pragma unroll
            for (int q = 0; q < 8; q++)
                p = fmaf(o[q], Wl[(k + q) * OUT_CH + cidx], p);
            // reduce within the 16-lane half
            p += __shfl_xor_sync(0xffffffffu, p, 8);
            p += __shfl_xor_sync(0xffffffffu, p, 4);
            p += __shfl_xor_sync(0xffffffffu, p, 2);
            p += __shfl_xor_sync(0xffffffffu, p, 1);
            if (l16 == 0) g_H6[(size_t)node * OUT_CH + cidx] = tanhf(p + bl[cidx]);
        }
    }
}

// ---------------- Pool ----------------
__global__ __launch_bounds__(256)
void pool_kernel(float* __restrict__ out) {
    const int g = blockIdx.x;
    __shared__ int s_lo, s_hi;
    __shared__ float ssum[OUT_CH];
    if (threadIdx.x == 0) {
        int lo = 0, hi = N_NODES;
        while (lo < hi) { int m = (lo + hi) >> 1; if (g_batch[m] < g) lo = m + 1; else hi = m; }
        s_lo = lo;
        int lo2 = lo, hi2 = N_NODES;
        while (lo2 < hi2) { int m = (lo2 + hi2) >> 1; if (g_batch[m] < g + 1) lo2 = m + 1; else hi2 = m; }
        s_hi = lo2;
    }
    if (threadIdx.x < OUT_CH) ssum[threadIdx.x] = 0.0f;
    __syncthreads();
    int lo = s_lo, hi = s_hi;
    float loc[OUT_CH];
#pragma unroll
    for (int c = 0; c < OUT_CH; c++) loc[c] = 0.0f;
    for (int i = lo + threadIdx.x; i < hi; i += blockDim.x) {
#pragma unroll
        for (int c = 0; c < OUT_CH; c++) loc[c] += g_H6[(size_t)i * OUT_CH + c];
    }
#pragma unroll
    for (int c = 0; c < OUT_CH; c++) {
#pragma unroll
        for (int off = 16; off > 0; off >>= 1)
            loc[c] += __shfl_xor_sync(0xffffffffu, loc[c], off);
    }
    if ((threadIdx.x & 31) == 0) {
#pragma unroll
        for (int c = 0; c < OUT_CH; c++) atomicAdd(&ssum[c], loc[c]);
    }
    __syncthreads();
    if (threadIdx.x < OUT_CH) {
        float cnt = (float)(hi - lo);
        if (cnt < 1.0f) cnt = 1.0f;
        out[g * OUT_CH + threadIdx.x] = ssum[threadIdx.x] / cnt;
    }
}

// ---------------- launch ----------------
extern "C" void kernel_launch(void* const* d_in, const int* in_sizes, int n_in,
                              void* d_out, int out_size) {
    const float* x   = (const float*)d_in[0];
    const void*  ei  = d_in[1];
    const void*  bat = d_in[2];
    const float* W0  = (const float*)d_in[3];
    const float* b0  = (const float*)d_in[4];
    const float* W1  = (const float*)d_in[5];
    const float* b1  = (const float*)d_in[6];
    const float* W2  = (const float*)d_in[7];
    const float* b2  = (const float*)d_in[8];
    const float* Wl  = (const float*)d_in[9];
    const float* bl  = (const float*)d_in[10];
    float* out = (float*)d_out;

    __half* Wpk;
    cudaGetSymbolAddress((void**)&Wpk, g_Wpk16);

    cudaFuncSetAttribute(gemm_fp16_kernel<false>,
                         cudaFuncAttributeMaxDynamicSharedMemorySize,
                         GEMM_SMEM_BYTES);
    cudaFuncSetAttribute(gemm_fp16_kernel<true>,
                         cudaFuncAttributeMaxDynamicSharedMemorySize,
                         GEMM_SMEM_BYTES);

    prep_kernel<<<(N_NODES + 255) / 256, 256>>>((const unsigned int*)ei, W0, W1, W2);
    convfill_kernel<<<782, 256>>>(ei, bat);
    pad_kernel<<<(N_NODES + 255) / 256, 256>>>();

    const int gemm_grid = (N_NODES + TILE_M - 1) / TILE_M;   // 391
    const int agg_grid  = (N_NODES / 2 * 32 + 255) / 256;    // 2 nodes per warp -> 3125

    gemm_fp16_kernel<false><<<gemm_grid, 256, GEMM_SMEM_BYTES>>>(x, Wpk);
    agg_kernel_t<false><<<agg_grid, 256>>>(b0, Wl, bl);
    gemm_fp16_kernel<true><<<gemm_grid, 256, GEMM_SMEM_BYTES>>>(nullptr, Wpk + 128 * 128);
    agg_kernel_t<false><<<agg_grid, 256>>>(b1, Wl, bl);
    gemm_fp16_kernel<true><<<gemm_grid, 256, GEMM_SMEM_BYTES>>>(nullptr, Wpk + 2 * 128 * 128);
    agg_kernel_t<true><<<agg_grid, 256>>>(b2, Wl, bl);

    pool_kernel<<<N_GRAPHS, 256>>>(out);
}